// round 1
// baseline (speedup 1.0000x reference)
#include <cuda_runtime.h>
#include <math.h>

#define B_   8
#define T_   64
#define CIN_ 64
#define L_   256
#define F_   128
#define CO_  512   // 4*F

// Scratch (device globals — no runtime allocation allowed).
// g_Ax reused by both layers: [512 batches, 512 co, 256 l]
__device__ float g_Ax[(size_t)512 * CO_ * L_];
__device__ float g_hs0[(size_t)T_ * B_ * F_ * L_];
__device__ float g_c0s[(size_t)B_ * F_ * L_];
__device__ float g_c1s[(size_t)B_ * F_ * L_];

__device__ __forceinline__ float sigm(float x) { return 1.0f / (1.0f + expf(-x)); }

// ---------------------------------------------------------------------------
// Parallel precompute: out[n,co,l] = bias[co] + sum_{ci<Cx} sum_k W[co, c0w+ci, k] * X[n, ci, l+k-2]
// Block tile: 64 co x 128 l, 256 threads (16x16), thread tile 4 co x 8 l.
// K-loop over ci in chunks of 16 (Cx must be multiple of 16).
// ---------------------------------------------------------------------------
__global__ __launch_bounds__(256) void conv_gemm_kernel(
    const float* __restrict__ X,     // [NB, Cx, L]
    const float* __restrict__ W,     // [CO, CW, 5]
    const float* __restrict__ bias,  // [CO]
    float* __restrict__ out,         // [NB, CO, L]
    int Cx, int CW, int c0w)
{
    __shared__ float Ws[80][64];     // [ci*5+k][co_local]
    __shared__ float Xs[16][136];    // [ci][col], col = l_local + 2 (halo), row 544B (16B aligned)

    const int tid = threadIdx.x;
    const int tx = tid & 15, ty = tid >> 4;
    const int l0  = blockIdx.x * 128;
    const int co0 = blockIdx.y * 64;
    const int n   = blockIdx.z;

    const float* Xn = X + (size_t)n * Cx * L_;

    float acc[4][8];
    #pragma unroll
    for (int i = 0; i < 4; i++)
        #pragma unroll
        for (int j = 0; j < 8; j++) acc[i][j] = 0.f;

    const int wRow  = tid >> 2;   // 0..63 co_local
    const int wPart = tid & 3;    // 0..3 -> 20 consecutive (ci,k) elems each
    const int nCh = Cx >> 4;

    for (int ch = 0; ch < nCh; ch++) {
        const int cc = ch << 4;
        // W chunk: 80 contiguous floats per co row ((c0w+cc)*5 .. +79)
        {
            const float* wp = W + (size_t)(co0 + wRow) * CW * 5 + (c0w + cc) * 5 + wPart * 20;
            #pragma unroll
            for (int e = 0; e < 20; e++)
                Ws[wPart * 20 + e][wRow] = wp[e];
        }
        // X chunk: 16 ci x 132 cols with halo, zero-padded at edges
        for (int i = tid; i < 16 * 132; i += 256) {
            int ci = i / 132, col = i - ci * 132;
            int gl = l0 + col - 2;
            float v = 0.f;
            if (gl >= 0 && gl < L_) v = Xn[(size_t)(cc + ci) * L_ + gl];
            Xs[ci][col] = v;
        }
        __syncthreads();

        for (int ci = 0; ci < 16; ci++) {
            float xr[13];
            {
                const float* row = &Xs[ci][tx * 8];
                float4 q0 = *(const float4*)(row);
                float4 q1 = *(const float4*)(row + 4);
                float4 q2 = *(const float4*)(row + 8);
                xr[0]=q0.x; xr[1]=q0.y; xr[2]=q0.z; xr[3]=q0.w;
                xr[4]=q1.x; xr[5]=q1.y; xr[6]=q1.z; xr[7]=q1.w;
                xr[8]=q2.x; xr[9]=q2.y; xr[10]=q2.z; xr[11]=q2.w;
                xr[12] = row[12];
            }
            #pragma unroll
            for (int k = 0; k < 5; k++) {
                float wv[4];
                #pragma unroll
                for (int cj = 0; cj < 4; cj++) wv[cj] = Ws[ci * 5 + k][ty * 4 + cj];
                #pragma unroll
                for (int cj = 0; cj < 4; cj++)
                    #pragma unroll
                    for (int jl = 0; jl < 8; jl++)
                        acc[cj][jl] += wv[cj] * xr[jl + k];
            }
        }
        __syncthreads();
    }

    #pragma unroll
    for (int cj = 0; cj < 4; cj++) {
        int co = co0 + ty * 4 + cj;
        float bv = bias[co];
        float* op = out + ((size_t)n * CO_ + co) * L_ + l0 + tx * 8;
        #pragma unroll
        for (int jl = 0; jl < 8; jl++) op[jl] = acc[cj][jl] + bv;
    }
}

// ---------------------------------------------------------------------------
// Fused recurrent step: gates = Ax + conv(h_prev, W[:, choff:choff+F]) ; LSTM update.
// Block tile: 16 f x 4 gates x 64 l, 256 threads (16x16).
// Thread owns 1 f, all 4 gates, 4 l -> LSTM update fully thread-local.
// ---------------------------------------------------------------------------
__global__ __launch_bounds__(256) void lstm_step_kernel(
    const float* __restrict__ Hprev, // [B, F, L]
    const float* __restrict__ W,     // [CO, CW, 5]
    const float* __restrict__ Ax_t,  // base for this timestep
    size_t axStrideB,                // Ax batch stride (floats)
    const float* __restrict__ Cprev, // [B, F, L]
    float* __restrict__ Cout,        // [B, F, L]
    float* __restrict__ Hout,        // [B, F, L] slice of hs0 / d_out
    int CW, int choff)
{
    __shared__ float Ws[80][64];     // [ci*5+k][m], m = g*16 + f_local
    __shared__ float Xs[16][72];     // [ci][col], row 288B (16B aligned)

    const int tid = threadIdx.x;
    const int tx = tid & 15, ty = tid >> 4;
    const int l0 = blockIdx.x * 64;
    const int f0 = blockIdx.y * 16;
    const int b  = blockIdx.z;

    const float* Hb = Hprev + (size_t)b * F_ * L_;

    float acc[4][4];
    #pragma unroll
    for (int g = 0; g < 4; g++)
        #pragma unroll
        for (int j = 0; j < 4; j++) acc[g][j] = 0.f;

    const int wRow  = tid >> 2;             // m = g*16 + fl
    const int wPart = tid & 3;
    const int gW = wRow >> 4, flW = wRow & 15;
    const int coW = gW * F_ + f0 + flW;

    for (int ch = 0; ch < (F_ >> 4); ch++) {
        const int cc = ch << 4;
        {
            const float* wp = W + (size_t)coW * CW * 5 + (choff + cc) * 5 + wPart * 20;
            #pragma unroll
            for (int e = 0; e < 20; e++)
                Ws[wPart * 20 + e][wRow] = wp[e];
        }
        for (int i = tid; i < 16 * 68; i += 256) {
            int ci = i / 68, col = i - ci * 68;
            int gl = l0 + col - 2;
            float v = 0.f;
            if (gl >= 0 && gl < L_) v = Hb[(size_t)(cc + ci) * L_ + gl];
            Xs[ci][col] = v;
        }
        __syncthreads();

        for (int ci = 0; ci < 16; ci++) {
            float xr[9];
            {
                const float* row = &Xs[ci][tx * 4];
                float4 q0 = *(const float4*)(row);
                float4 q1 = *(const float4*)(row + 4);
                xr[0]=q0.x; xr[1]=q0.y; xr[2]=q0.z; xr[3]=q0.w;
                xr[4]=q1.x; xr[5]=q1.y; xr[6]=q1.z; xr[7]=q1.w;
                xr[8] = row[8];
            }
            #pragma unroll
            for (int k = 0; k < 5; k++) {
                float wv[4];
                #pragma unroll
                for (int g = 0; g < 4; g++) wv[g] = Ws[ci * 5 + k][g * 16 + ty];
                #pragma unroll
                for (int g = 0; g < 4; g++)
                    #pragma unroll
                    for (int jl = 0; jl < 4; jl++)
                        acc[g][jl] += wv[g] * xr[jl + k];
            }
        }
        __syncthreads();
    }

    // Epilogue: add Ax, gates, LSTM update
    const int f = f0 + ty;
    #pragma unroll
    for (int jl = 0; jl < 4; jl++) {
        int l = l0 + tx * 4 + jl;
        float A[4];
        #pragma unroll
        for (int g = 0; g < 4; g++)
            A[g] = acc[g][jl] + Ax_t[(size_t)b * axStrideB + (size_t)(g * F_ + f) * L_ + l];
        float ig = sigm(A[0]);       // input gate
        float fg = sigm(A[1]);       // forget gate
        float og = sigm(A[2]);       // output gate
        float gg = tanhf(A[3]);      // candidate
        size_t idx = ((size_t)b * F_ + f) * L_ + l;
        float cn = fg * Cprev[idx] + ig * gg;
        Cout[idx] = cn;
        Hout[idx] = og * tanhf(cn);
    }
}

// ---------------------------------------------------------------------------
extern "C" void kernel_launch(void* const* d_in, const int* in_sizes, int n_in,
                              void* d_out, int out_size)
{
    const float* x  = (const float*)d_in[0];  // [B, T, Cin, L]
    const float* W0 = (const float*)d_in[1];  // [512, 192, 5]
    const float* b0 = (const float*)d_in[2];  // [512]
    const float* W1 = (const float*)d_in[3];  // [512, 256, 5]
    const float* b1 = (const float*)d_in[4];  // [512]
    const float* h0 = (const float*)d_in[5];  // [B, F, L]
    const float* c0 = (const float*)d_in[6];
    const float* h1 = (const float*)d_in[7];
    const float* c1 = (const float*)d_in[8];
    float* out = (float*)d_out;               // [T, B, F, L]

    float *Ax, *hs0, *c0s, *c1s;
    cudaGetSymbolAddress((void**)&Ax,  g_Ax);
    cudaGetSymbolAddress((void**)&hs0, g_hs0);
    cudaGetSymbolAddress((void**)&c0s, g_c0s);
    cudaGetSymbolAddress((void**)&c1s, g_c1s);

    const dim3 blk(256);
    const size_t BFL = (size_t)B_ * F_ * L_;

    // Phase 1: Ax0[n=b*T+t] = bias0 + conv(x_t, W0[:, :Cin])  (x is already [B*T, Cin, L])
    conv_gemm_kernel<<<dim3(2, 8, 512), blk>>>(x, W0, b0, Ax, CIN_, CIN_ + F_, 0);

    // Phase 2: layer-0 recurrence. Ax batch index n = b*T + t.
    for (int t = 0; t < T_; t++) {
        const float* Hp = (t == 0) ? h0 : hs0 + (size_t)(t - 1) * BFL;
        const float* Cp = (t == 0) ? c0 : c0s;
        lstm_step_kernel<<<dim3(4, 8, 8), blk>>>(
            Hp, W0,
            Ax + (size_t)t * CO_ * L_, (size_t)T_ * CO_ * L_,
            Cp, c0s, hs0 + (size_t)t * BFL,
            CIN_ + F_, CIN_);
    }

    // Phase 3: Ax1[n=t*B+b] = bias1 + conv(hs0, W1[:, :F])  (hs0 is [T*B, F, L])
    conv_gemm_kernel<<<dim3(2, 8, 512), blk>>>(hs0, W1, b1, Ax, F_, 2 * F_, 0);

    // Phase 4: layer-1 recurrence, writes d_out[t] directly. Ax batch index n = t*B + b.
    for (int t = 0; t < T_; t++) {
        const float* Hp = (t == 0) ? h1 : out + (size_t)(t - 1) * BFL;
        const float* Cp = (t == 0) ? c1 : c1s;
        lstm_step_kernel<<<dim3(4, 8, 8), blk>>>(
            Hp, W1,
            Ax + (size_t)t * B_ * CO_ * L_, (size_t)CO_ * L_,
            Cp, c1s, out + (size_t)t * BFL,
            2 * F_, F_);
    }
}

// round 2
// speedup vs baseline: 1.0666x; 1.0666x over previous
#include <cuda_runtime.h>
#include <math.h>

#define B_   8
#define T_   64
#define CIN_ 64
#define L_   256
#define F_   128
#define CO_  512   // 4*F

// Scratch (device globals — no runtime allocation allowed).
__device__ float g_Ax[(size_t)512 * CO_ * L_];
__device__ float g_hs0[(size_t)T_ * B_ * F_ * L_];
__device__ float g_c0s[(size_t)B_ * F_ * L_];
__device__ float g_c1s[(size_t)B_ * F_ * L_];

__device__ __forceinline__ float sigm(float x) { return 1.0f / (1.0f + expf(-x)); }

// ---------------------------------------------------------------------------
// Parallel precompute: out[n,co,l] = bias[co] + sum_{ci<Cx} sum_k W[co, c0w+ci, k] * X[n, ci, l+k-2]
// Block tile: 64 co x 128 l, 256 threads (16x16), thread tile 4 co x 8 l.
// Weights in smem as float4 over 4 consecutive co -> one LDS.128 per (ci,k).
// ---------------------------------------------------------------------------
__global__ __launch_bounds__(256) void conv_gemm_kernel(
    const float* __restrict__ X,     // [NB, Cx, L]
    const float* __restrict__ W,     // [CO, CW, 5]
    const float* __restrict__ bias,  // [CO]
    float* __restrict__ out,         // [NB, CO, L]
    int Cx, int CW, int c0w)
{
    __shared__ float4 Ws4[80][16];   // [ci*5+k][co_group of 4]
    __shared__ float  Xs[16][136];   // [ci][col], col = l_local + 2 (halo)

    const int tid = threadIdx.x;
    const int tx = tid & 15, ty = tid >> 4;
    const int l0  = blockIdx.x * 128;
    const int co0 = blockIdx.y * 64;
    const int n   = blockIdx.z;

    const float* Xn = X + (size_t)n * Cx * L_;

    float acc[4][8];
    #pragma unroll
    for (int i = 0; i < 4; i++)
        #pragma unroll
        for (int j = 0; j < 8; j++) acc[i][j] = 0.f;

    const int wRow  = tid >> 2;   // 0..63 co_local
    const int wPart = tid & 3;    // 0..3 -> 20 consecutive (ci,k) elems each
    const int nCh = Cx >> 4;

    for (int ch = 0; ch < nCh; ch++) {
        const int cc = ch << 4;
        {
            const float* wp = W + (size_t)(co0 + wRow) * CW * 5 + (c0w + cc) * 5 + wPart * 20;
            #pragma unroll
            for (int e = 0; e < 20; e++)
                ((float*)&Ws4[wPart * 20 + e][wRow >> 2])[wRow & 3] = wp[e];
        }
        for (int i = tid; i < 16 * 132; i += 256) {
            int ci = i / 132, col = i - ci * 132;
            int gl = l0 + col - 2;
            float v = 0.f;
            if (gl >= 0 && gl < L_) v = Xn[(size_t)(cc + ci) * L_ + gl];
            Xs[ci][col] = v;
        }
        __syncthreads();

        for (int ci = 0; ci < 16; ci++) {
            float xr[13];
            {
                const float* row = &Xs[ci][tx * 8];
                float4 q0 = *(const float4*)(row);
                float4 q1 = *(const float4*)(row + 4);
                float4 q2 = *(const float4*)(row + 8);
                xr[0]=q0.x; xr[1]=q0.y; xr[2]=q0.z; xr[3]=q0.w;
                xr[4]=q1.x; xr[5]=q1.y; xr[6]=q1.z; xr[7]=q1.w;
                xr[8]=q2.x; xr[9]=q2.y; xr[10]=q2.z; xr[11]=q2.w;
                xr[12] = row[12];
            }
            #pragma unroll
            for (int k = 0; k < 5; k++) {
                float4 w4 = Ws4[ci * 5 + k][ty];
                float wv[4] = {w4.x, w4.y, w4.z, w4.w};
                #pragma unroll
                for (int cj = 0; cj < 4; cj++)
                    #pragma unroll
                    for (int jl = 0; jl < 8; jl++)
                        acc[cj][jl] += wv[cj] * xr[jl + k];
            }
        }
        __syncthreads();
    }

    #pragma unroll
    for (int cj = 0; cj < 4; cj++) {
        int co = co0 + ty * 4 + cj;
        float bv = bias[co];
        float* op = out + ((size_t)n * CO_ + co) * L_ + l0 + tx * 8;
        float4 o0 = make_float4(acc[cj][0]+bv, acc[cj][1]+bv, acc[cj][2]+bv, acc[cj][3]+bv);
        float4 o1 = make_float4(acc[cj][4]+bv, acc[cj][5]+bv, acc[cj][6]+bv, acc[cj][7]+bv);
        *(float4*)(op)     = o0;
        *(float4*)(op + 4) = o1;
    }
}

// ---------------------------------------------------------------------------
// Fused recurrent step: gates = Ax + conv(h_prev, W[:, choff:choff+F]) ; LSTM update.
// Block tile: 16 f x 4 gates x 64 l, 256 threads (16x16).
// Thread owns 1 f, all 4 gates, 4 l. Weights gate-contiguous in smem (float4).
// ---------------------------------------------------------------------------
__global__ __launch_bounds__(256) void lstm_step_kernel(
    const float* __restrict__ Hprev, // [B, F, L]
    const float* __restrict__ W,     // [CO, CW, 5]
    const float* __restrict__ Ax_t,  // base for this timestep
    size_t axStrideB,                // Ax batch stride (floats)
    const float* __restrict__ Cprev, // [B, F, L]
    float* __restrict__ Cout,        // [B, F, L]
    float* __restrict__ Hout,        // [B, F, L]
    int CW, int choff)
{
    __shared__ float4 Ws4[80][16];   // [ci*5+k][f_local], components = gates
    __shared__ float  Xs[16][72];    // [ci][col]

    const int tid = threadIdx.x;
    const int tx = tid & 15, ty = tid >> 4;
    const int l0 = blockIdx.x * 64;
    const int f0 = blockIdx.y * 16;
    const int b  = blockIdx.z;

    const float* Hb = Hprev + (size_t)b * F_ * L_;

    float acc[4][4];
    #pragma unroll
    for (int g = 0; g < 4; g++)
        #pragma unroll
        for (int j = 0; j < 4; j++) acc[g][j] = 0.f;

    const int wRow  = tid >> 2;             // m = g*16 + fl
    const int wPart = tid & 3;
    const int gW = wRow >> 4, flW = wRow & 15;
    const int coW = gW * F_ + f0 + flW;

    for (int ch = 0; ch < (F_ >> 4); ch++) {
        const int cc = ch << 4;
        {
            const float* wp = W + (size_t)coW * CW * 5 + (choff + cc) * 5 + wPart * 20;
            #pragma unroll
            for (int e = 0; e < 20; e++)
                ((float*)&Ws4[wPart * 20 + e][flW])[gW] = wp[e];
        }
        for (int i = tid; i < 16 * 68; i += 256) {
            int ci = i / 68, col = i - ci * 68;
            int gl = l0 + col - 2;
            float v = 0.f;
            if (gl >= 0 && gl < L_) v = Hb[(size_t)(cc + ci) * L_ + gl];
            Xs[ci][col] = v;
        }
        __syncthreads();

        for (int ci = 0; ci < 16; ci++) {
            float xr[9];
            {
                const float* row = &Xs[ci][tx * 4];
                float4 q0 = *(const float4*)(row);
                float4 q1 = *(const float4*)(row + 4);
                xr[0]=q0.x; xr[1]=q0.y; xr[2]=q0.z; xr[3]=q0.w;
                xr[4]=q1.x; xr[5]=q1.y; xr[6]=q1.z; xr[7]=q1.w;
                xr[8] = row[8];
            }
            #pragma unroll
            for (int k = 0; k < 5; k++) {
                float4 w4 = Ws4[ci * 5 + k][ty];
                float wv[4] = {w4.x, w4.y, w4.z, w4.w};
                #pragma unroll
                for (int g = 0; g < 4; g++)
                    #pragma unroll
                    for (int jl = 0; jl < 4; jl++)
                        acc[g][jl] += wv[g] * xr[jl + k];
            }
        }
        __syncthreads();
    }

    // Epilogue: add Ax (vectorized), gates, LSTM update (vectorized I/O).
    const int f = f0 + ty;
    const int l = l0 + tx * 4;
    const float* axb = Ax_t + (size_t)b * axStrideB + (size_t)f * L_ + l;
    float4 A0 = *(const float4*)(axb + (size_t)0 * F_ * L_);
    float4 A1 = *(const float4*)(axb + (size_t)1 * F_ * L_);
    float4 A2 = *(const float4*)(axb + (size_t)2 * F_ * L_);
    float4 A3 = *(const float4*)(axb + (size_t)3 * F_ * L_);

    const size_t idx = ((size_t)b * F_ + f) * L_ + l;
    float4 cp = *(const float4*)&Cprev[idx];

    float Ai[4] = {A0.x+acc[0][0], A0.y+acc[0][1], A0.z+acc[0][2], A0.w+acc[0][3]};
    float Af[4] = {A1.x+acc[1][0], A1.y+acc[1][1], A1.z+acc[1][2], A1.w+acc[1][3]};
    float Ao[4] = {A2.x+acc[2][0], A2.y+acc[2][1], A2.z+acc[2][2], A2.w+acc[2][3]};
    float Ag[4] = {A3.x+acc[3][0], A3.y+acc[3][1], A3.z+acc[3][2], A3.w+acc[3][3]};
    float cpv[4] = {cp.x, cp.y, cp.z, cp.w};

    float cn[4], hn[4];
    #pragma unroll
    for (int jl = 0; jl < 4; jl++) {
        float ig = sigm(Ai[jl]);
        float fg = sigm(Af[jl]);
        float og = sigm(Ao[jl]);
        float gg = tanhf(Ag[jl]);
        cn[jl] = fg * cpv[jl] + ig * gg;
        hn[jl] = og * tanhf(cn[jl]);
    }
    *(float4*)&Cout[idx] = make_float4(cn[0], cn[1], cn[2], cn[3]);
    *(float4*)&Hout[idx] = make_float4(hn[0], hn[1], hn[2], hn[3]);
}

// ---------------------------------------------------------------------------
extern "C" void kernel_launch(void* const* d_in, const int* in_sizes, int n_in,
                              void* d_out, int out_size)
{
    const float* x  = (const float*)d_in[0];  // [B, T, Cin, L]
    const float* W0 = (const float*)d_in[1];  // [512, 192, 5]
    const float* b0 = (const float*)d_in[2];  // [512]
    const float* W1 = (const float*)d_in[3];  // [512, 256, 5]
    const float* b1 = (const float*)d_in[4];  // [512]
    const float* h0 = (const float*)d_in[5];  // [B, F, L]
    const float* c0 = (const float*)d_in[6];
    const float* h1 = (const float*)d_in[7];
    const float* c1 = (const float*)d_in[8];
    float* out = (float*)d_out;               // [T, B, F, L]

    float *Ax, *hs0, *c0s, *c1s;
    cudaGetSymbolAddress((void**)&Ax,  g_Ax);
    cudaGetSymbolAddress((void**)&hs0, g_hs0);
    cudaGetSymbolAddress((void**)&c0s, g_c0s);
    cudaGetSymbolAddress((void**)&c1s, g_c1s);

    const dim3 blk(256);
    const size_t BFL = (size_t)B_ * F_ * L_;

    // Phase 1: Ax0[n=b*T+t] = bias0 + conv(x_t, W0[:, :Cin])
    conv_gemm_kernel<<<dim3(2, 8, 512), blk>>>(x, W0, b0, Ax, CIN_, CIN_ + F_, 0);

    // Phase 2: layer-0 recurrence. Ax batch index n = b*T + t.
    for (int t = 0; t < T_; t++) {
        const float* Hp = (t == 0) ? h0 : hs0 + (size_t)(t - 1) * BFL;
        const float* Cp = (t == 0) ? c0 : c0s;
        lstm_step_kernel<<<dim3(4, 8, 8), blk>>>(
            Hp, W0,
            Ax + (size_t)t * CO_ * L_, (size_t)T_ * CO_ * L_,
            Cp, c0s, hs0 + (size_t)t * BFL,
            CIN_ + F_, CIN_);
    }

    // Phase 3: Ax1[n=t*B+b] = bias1 + conv(hs0, W1[:, :F])
    conv_gemm_kernel<<<dim3(2, 8, 512), blk>>>(hs0, W1, b1, Ax, F_, 2 * F_, 0);

    // Phase 4: layer-1 recurrence, writes d_out[t] directly.
    for (int t = 0; t < T_; t++) {
        const float* Hp = (t == 0) ? h1 : out + (size_t)(t - 1) * BFL;
        const float* Cp = (t == 0) ? c1 : c1s;
        lstm_step_kernel<<<dim3(4, 8, 8), blk>>>(
            Hp, W1,
            Ax + (size_t)t * B_ * CO_ * L_, (size_t)CO_ * L_,
            Cp, c1s, out + (size_t)t * BFL,
            2 * F_, F_);
    }
}

// round 3
// speedup vs baseline: 1.1257x; 1.0553x over previous
#include <cuda_runtime.h>
#include <math.h>

#define B_   8
#define T_   64
#define CIN_ 64
#define L_   256
#define F_   128
#define CO_  512   // 4*F

// Scratch (device globals — no runtime allocation allowed).
__device__ float g_Ax[(size_t)512 * CO_ * L_];
__device__ float g_hs0[(size_t)T_ * B_ * F_ * L_];
__device__ float g_c0s[(size_t)B_ * F_ * L_];
__device__ float g_c1s[(size_t)B_ * F_ * L_];

__device__ __forceinline__ float sigm(float x) { return 1.0f / (1.0f + expf(-x)); }

// ---- packed f32x2 helpers -------------------------------------------------
__device__ __forceinline__ unsigned long long bcast2(float v) {
    unsigned long long r;
    asm("mov.b64 %0, {%1, %1};" : "=l"(r) : "f"(v));
    return r;
}
__device__ __forceinline__ float2 unpack2(unsigned long long p) {
    float2 r;
    asm("mov.b64 {%0, %1}, %2;" : "=f"(r.x), "=f"(r.y) : "l"(p));
    return r;
}
#define FMA2(acc, w, x) \
    asm("fma.rn.f32x2 %0, %1, %2, %0;" : "+l"(acc) : "l"(w), "l"(x))

// ---------------------------------------------------------------------------
// Parallel precompute: out[n,co,l] = bias[co] + sum_{ci<Cx} sum_k W[co, c0w+ci, k] * X[n, ci, l+k-2]
// Block tile: 64 co x 128 l, 256 threads (16x16), thread tile 4 co x 8 l.
// FFMA2: co pairs packed (smem float4 read as ulonglong2), x broadcast-packed.
// ---------------------------------------------------------------------------
__global__ __launch_bounds__(256) void conv_gemm_kernel(
    const float* __restrict__ X,     // [NB, Cx, L]
    const float* __restrict__ W,     // [CO, CW, 5]
    const float* __restrict__ bias,  // [CO]
    float* __restrict__ out,         // [NB, CO, L]
    int Cx, int CW, int c0w)
{
    __shared__ float4 Ws4[80][16];   // [ci*5+k][co_group of 4]
    __shared__ float  Xs[16][136];   // [ci][col], col = l_local + 2 (halo)

    const int tid = threadIdx.x;
    const int tx = tid & 15, ty = tid >> 4;
    const int l0  = blockIdx.x * 128;
    const int co0 = blockIdx.y * 64;
    const int n   = blockIdx.z;

    const float* Xn = X + (size_t)n * Cx * L_;

    unsigned long long accp[2][8];   // [co-pair][l], each = 2 co lanes
    #pragma unroll
    for (int p = 0; p < 2; p++)
        #pragma unroll
        for (int j = 0; j < 8; j++) accp[p][j] = 0ULL;

    const int wRow  = tid >> 2;   // 0..63 co_local
    const int wPart = tid & 3;    // 0..3 -> 20 consecutive (ci,k) elems each
    const int nCh = Cx >> 4;

    for (int ch = 0; ch < nCh; ch++) {
        const int cc = ch << 4;
        {
            const float* wp = W + (size_t)(co0 + wRow) * CW * 5 + (c0w + cc) * 5 + wPart * 20;
            #pragma unroll
            for (int e = 0; e < 20; e++)
                ((float*)&Ws4[wPart * 20 + e][wRow >> 2])[wRow & 3] = wp[e];
        }
        for (int i = tid; i < 16 * 132; i += 256) {
            int ci = i / 132, col = i - ci * 132;
            int gl = l0 + col - 2;
            float v = 0.f;
            if (gl >= 0 && gl < L_) v = Xn[(size_t)(cc + ci) * L_ + gl];
            Xs[ci][col] = v;
        }
        __syncthreads();

        for (int ci = 0; ci < 16; ci++) {
            float xr[12];
            {
                const float* row = &Xs[ci][tx * 8];
                float4 q0 = *(const float4*)(row);
                float4 q1 = *(const float4*)(row + 4);
                float4 q2 = *(const float4*)(row + 8);
                xr[0]=q0.x; xr[1]=q0.y; xr[2]=q0.z; xr[3]=q0.w;
                xr[4]=q1.x; xr[5]=q1.y; xr[6]=q1.z; xr[7]=q1.w;
                xr[8]=q2.x; xr[9]=q2.y; xr[10]=q2.z; xr[11]=q2.w;
            }
            unsigned long long xb[12];
            #pragma unroll
            for (int j = 0; j < 12; j++) xb[j] = bcast2(xr[j]);

            #pragma unroll
            for (int k = 0; k < 5; k++) {
                ulonglong2 wp = *(const ulonglong2*)&Ws4[ci * 5 + k][ty];
                #pragma unroll
                for (int jl = 0; jl < 8; jl++) {
                    FMA2(accp[0][jl], wp.x, xb[jl + k]);
                    FMA2(accp[1][jl], wp.y, xb[jl + k]);
                }
            }
        }
        __syncthreads();
    }

    #pragma unroll
    for (int p = 0; p < 2; p++) {
        float o[2][8];
        #pragma unroll
        for (int jl = 0; jl < 8; jl++) {
            float2 v = unpack2(accp[p][jl]);
            o[0][jl] = v.x; o[1][jl] = v.y;
        }
        #pragma unroll
        for (int q = 0; q < 2; q++) {
            int co = co0 + ty * 4 + p * 2 + q;
            float bv = bias[co];
            float* op = out + ((size_t)n * CO_ + co) * L_ + l0 + tx * 8;
            *(float4*)(op)     = make_float4(o[q][0]+bv, o[q][1]+bv, o[q][2]+bv, o[q][3]+bv);
            *(float4*)(op + 4) = make_float4(o[q][4]+bv, o[q][5]+bv, o[q][6]+bv, o[q][7]+bv);
        }
    }
}

// ---------------------------------------------------------------------------
// Fused recurrent step: gates = Ax + conv(h_prev, W[:, choff:choff+F]) ; LSTM update.
// Block tile: 16 f x 4 gates x 64 l, 256 threads (16x16).
// Thread owns 1 f, all 4 gates, 4 l. FFMA2 over gate pairs.
// ---------------------------------------------------------------------------
__global__ __launch_bounds__(256) void lstm_step_kernel(
    const float* __restrict__ Hprev, // [B, F, L]
    const float* __restrict__ W,     // [CO, CW, 5]
    const float* __restrict__ Ax_t,  // base for this timestep
    size_t axStrideB,                // Ax batch stride (floats)
    const float* __restrict__ Cprev, // [B, F, L]
    float* __restrict__ Cout,        // [B, F, L]
    float* __restrict__ Hout,        // [B, F, L]
    int CW, int choff)
{
    __shared__ float4 Ws4[80][16];   // [ci*5+k][f_local], components = gates 0..3
    __shared__ float  Xs[16][72];    // [ci][col]

    const int tid = threadIdx.x;
    const int tx = tid & 15, ty = tid >> 4;
    const int l0 = blockIdx.x * 64;
    const int f0 = blockIdx.y * 16;
    const int b  = blockIdx.z;

    const float* Hb = Hprev + (size_t)b * F_ * L_;

    unsigned long long accp[2][4];   // [gate-pair][l]
    #pragma unroll
    for (int p = 0; p < 2; p++)
        #pragma unroll
        for (int j = 0; j < 4; j++) accp[p][j] = 0ULL;

    const int wRow  = tid >> 2;             // m = g*16 + fl
    const int wPart = tid & 3;
    const int gW = wRow >> 4, flW = wRow & 15;
    const int coW = gW * F_ + f0 + flW;

    for (int ch = 0; ch < (F_ >> 4); ch++) {
        const int cc = ch << 4;
        {
            const float* wp = W + (size_t)coW * CW * 5 + (choff + cc) * 5 + wPart * 20;
            #pragma unroll
            for (int e = 0; e < 20; e++)
                ((float*)&Ws4[wPart * 20 + e][flW])[gW] = wp[e];
        }
        for (int i = tid; i < 16 * 68; i += 256) {
            int ci = i / 68, col = i - ci * 68;
            int gl = l0 + col - 2;
            float v = 0.f;
            if (gl >= 0 && gl < L_) v = Hb[(size_t)(cc + ci) * L_ + gl];
            Xs[ci][col] = v;
        }
        __syncthreads();

        for (int ci = 0; ci < 16; ci++) {
            float xr[8];
            {
                const float* row = &Xs[ci][tx * 4];
                float4 q0 = *(const float4*)(row);
                float4 q1 = *(const float4*)(row + 4);
                xr[0]=q0.x; xr[1]=q0.y; xr[2]=q0.z; xr[3]=q0.w;
                xr[4]=q1.x; xr[5]=q1.y; xr[6]=q1.z; xr[7]=q1.w;
            }
            unsigned long long xb[8];
            #pragma unroll
            for (int j = 0; j < 8; j++) xb[j] = bcast2(xr[j]);

            #pragma unroll
            for (int k = 0; k < 5; k++) {
                ulonglong2 wp = *(const ulonglong2*)&Ws4[ci * 5 + k][ty];
                #pragma unroll
                for (int jl = 0; jl < 4; jl++) {
                    FMA2(accp[0][jl], wp.x, xb[jl + k]);
                    FMA2(accp[1][jl], wp.y, xb[jl + k]);
                }
            }
        }
        __syncthreads();
    }

    // Unpack: accp[0] -> gates 0,1 ; accp[1] -> gates 2,3
    float acc[4][4];
    #pragma unroll
    for (int p = 0; p < 2; p++)
        #pragma unroll
        for (int jl = 0; jl < 4; jl++) {
            float2 v = unpack2(accp[p][jl]);
            acc[2 * p][jl]     = v.x;
            acc[2 * p + 1][jl] = v.y;
        }

    // Epilogue: add Ax (vectorized), gates, LSTM update (vectorized I/O).
    const int f = f0 + ty;
    const int l = l0 + tx * 4;
    const float* axb = Ax_t + (size_t)b * axStrideB + (size_t)f * L_ + l;
    float4 A0 = *(const float4*)(axb + (size_t)0 * F_ * L_);
    float4 A1 = *(const float4*)(axb + (size_t)1 * F_ * L_);
    float4 A2 = *(const float4*)(axb + (size_t)2 * F_ * L_);
    float4 A3 = *(const float4*)(axb + (size_t)3 * F_ * L_);

    const size_t idx = ((size_t)b * F_ + f) * L_ + l;
    float4 cp = *(const float4*)&Cprev[idx];

    float Ai[4] = {A0.x+acc[0][0], A0.y+acc[0][1], A0.z+acc[0][2], A0.w+acc[0][3]};
    float Af[4] = {A1.x+acc[1][0], A1.y+acc[1][1], A1.z+acc[1][2], A1.w+acc[1][3]};
    float Ao[4] = {A2.x+acc[2][0], A2.y+acc[2][1], A2.z+acc[2][2], A2.w+acc[2][3]};
    float Ag[4] = {A3.x+acc[3][0], A3.y+acc[3][1], A3.z+acc[3][2], A3.w+acc[3][3]};
    float cpv[4] = {cp.x, cp.y, cp.z, cp.w};

    float cn[4], hn[4];
    #pragma unroll
    for (int jl = 0; jl < 4; jl++) {
        float ig = sigm(Ai[jl]);
        float fg = sigm(Af[jl]);
        float og = sigm(Ao[jl]);
        float gg = tanhf(Ag[jl]);
        cn[jl] = fg * cpv[jl] + ig * gg;
        hn[jl] = og * tanhf(cn[jl]);
    }
    *(float4*)&Cout[idx] = make_float4(cn[0], cn[1], cn[2], cn[3]);
    *(float4*)&Hout[idx] = make_float4(hn[0], hn[1], hn[2], hn[3]);
}

// ---------------------------------------------------------------------------
extern "C" void kernel_launch(void* const* d_in, const int* in_sizes, int n_in,
                              void* d_out, int out_size)
{
    const float* x  = (const float*)d_in[0];  // [B, T, Cin, L]
    const float* W0 = (const float*)d_in[1];  // [512, 192, 5]
    const float* b0 = (const float*)d_in[2];  // [512]
    const float* W1 = (const float*)d_in[3];  // [512, 256, 5]
    const float* b1 = (const float*)d_in[4];  // [512]
    const float* h0 = (const float*)d_in[5];  // [B, F, L]
    const float* c0 = (const float*)d_in[6];
    const float* h1 = (const float*)d_in[7];
    const float* c1 = (const float*)d_in[8];
    float* out = (float*)d_out;               // [T, B, F, L]

    float *Ax, *hs0, *c0s, *c1s;
    cudaGetSymbolAddress((void**)&Ax,  g_Ax);
    cudaGetSymbolAddress((void**)&hs0, g_hs0);
    cudaGetSymbolAddress((void**)&c0s, g_c0s);
    cudaGetSymbolAddress((void**)&c1s, g_c1s);

    const dim3 blk(256);
    const size_t BFL = (size_t)B_ * F_ * L_;

    // Phase 1: Ax0[n=b*T+t] = bias0 + conv(x_t, W0[:, :Cin])
    conv_gemm_kernel<<<dim3(2, 8, 512), blk>>>(x, W0, b0, Ax, CIN_, CIN_ + F_, 0);

    // Phase 2: layer-0 recurrence. Ax batch index n = b*T + t.
    for (int t = 0; t < T_; t++) {
        const float* Hp = (t == 0) ? h0 : hs0 + (size_t)(t - 1) * BFL;
        const float* Cp = (t == 0) ? c0 : c0s;
        lstm_step_kernel<<<dim3(4, 8, 8), blk>>>(
            Hp, W0,
            Ax + (size_t)t * CO_ * L_, (size_t)T_ * CO_ * L_,
            Cp, c0s, hs0 + (size_t)t * BFL,
            CIN_ + F_, CIN_);
    }

    // Phase 3: Ax1[n=t*B+b] = bias1 + conv(hs0, W1[:, :F])
    conv_gemm_kernel<<<dim3(2, 8, 512), blk>>>(hs0, W1, b1, Ax, F_, 2 * F_, 0);

    // Phase 4: layer-1 recurrence, writes d_out[t] directly.
    for (int t = 0; t < T_; t++) {
        const float* Hp = (t == 0) ? h1 : out + (size_t)(t - 1) * BFL;
        const float* Cp = (t == 0) ? c1 : c1s;
        lstm_step_kernel<<<dim3(4, 8, 8), blk>>>(
            Hp, W1,
            Ax + (size_t)t * B_ * CO_ * L_, (size_t)CO_ * L_,
            Cp, c1s, out + (size_t)t * BFL,
            2 * F_, F_);
    }
}

// round 4
// speedup vs baseline: 1.5763x; 1.4003x over previous
#include <cuda_runtime.h>
#include <math.h>

#define B_   8
#define T_   64
#define CIN_ 64
#define L_   256
#define F_   128
#define CO_  512   // 4*F

// Scratch (device globals — no runtime allocation allowed).
__device__ float g_Ax[(size_t)512 * CO_ * L_];
__device__ float g_hs0[(size_t)T_ * B_ * F_ * L_];
__device__ float g_c0s[(size_t)B_ * F_ * L_];
__device__ float g_c1s[(size_t)B_ * F_ * L_];

__device__ __forceinline__ float sigm(float x) { return 1.0f / (1.0f + expf(-x)); }

__device__ __forceinline__ unsigned long long bcast2(float v) {
    unsigned long long r;
    asm("mov.b64 %0, {%1, %1};" : "=l"(r) : "f"(v));
    return r;
}
__device__ __forceinline__ float2 unpack2(unsigned long long p) {
    float2 r;
    asm("mov.b64 {%0, %1}, %2;" : "=f"(r.x), "=f"(r.y) : "l"(p));
    return r;
}
#define FMA2(acc, w, x) \
    asm("fma.rn.f32x2 %0, %1, %2, %0;" : "+l"(acc) : "l"(w), "l"(x))

extern __shared__ char dynsmem[];

// ---------------------------------------------------------------------------
// Parallel precompute conv. Block tile 64 co x 128 l, 256 thr, thread 4co x 8l.
// Double-buffered chunks: prefetch W/X of chunk ch+1 into regs during compute.
// dyn smem: Ws4[2][80][16] float4 (40960B) + Xs[2][16][136] float (17408B).
// ---------------------------------------------------------------------------
#define CONV_SMEM (2*80*16*16 + 2*16*136*4)
__global__ __launch_bounds__(256, 2) void conv_gemm_kernel(
    const float* __restrict__ X,     // [NB, Cx, L]
    const float* __restrict__ W,     // [CO, CW, 5]
    const float* __restrict__ bias,  // [CO]
    float* __restrict__ out,         // [NB, CO, L]
    int Cx, int CW, int c0w)
{
    float4* Wsm = (float4*)dynsmem;                              // [2][80][16]
    float*  Xsm = (float*)(dynsmem + 2*80*16*sizeof(float4));    // [2][16][136]

    const int tid = threadIdx.x;
    const int tx = tid & 15, ty = tid >> 4;
    const int l0  = blockIdx.x * 128;
    const int co0 = blockIdx.y * 64;
    const int n   = blockIdx.z;
    const float* Xn = X + (size_t)n * Cx * L_;

    const int wRow = tid >> 2, wPart = tid & 3;
    const int nCh = Cx >> 4;

    unsigned long long accp[2][8];
    #pragma unroll
    for (int p = 0; p < 2; p++)
        #pragma unroll
        for (int j = 0; j < 8; j++) accp[p][j] = 0ULL;

    float4 wv[5];
    float  xv[9];

    auto ldW = [&](int ch) {
        const float4* wp = (const float4*)(W + (size_t)(co0 + wRow) * CW * 5
                                             + (size_t)(c0w + (ch << 4)) * 5 + wPart * 20);
        #pragma unroll
        for (int e = 0; e < 5; e++) wv[e] = wp[e];
    };
    auto ldX = [&](int ch) {
        const float* Xc = Xn + (size_t)(ch << 4) * L_;
        #pragma unroll
        for (int r = 0; r < 9; r++) {
            int i = tid + (r << 8);
            if (i < 16 * 132) {
                int ci = i / 132, col = i - ci * 132;
                int gl = l0 + col - 2;
                xv[r] = (gl >= 0 && gl < L_) ? Xc[(size_t)ci * L_ + gl] : 0.f;
            }
        }
    };
    auto stWX = [&](int buf) {
        float4* Wb = Wsm + buf * 80 * 16;
        float*  Xb = Xsm + buf * 16 * 136;
        #pragma unroll
        for (int e = 0; e < 5; e++) {
            const float* f = (const float*)&wv[e];
            #pragma unroll
            for (int j = 0; j < 4; j++)
                ((float*)&Wb[(wPart * 20 + e * 4 + j) * 16 + (wRow >> 2)])[wRow & 3] = f[j];
        }
        #pragma unroll
        for (int r = 0; r < 9; r++) {
            int i = tid + (r << 8);
            if (i < 16 * 132) {
                int ci = i / 132;
                Xb[ci * 136 + (i - ci * 132)] = xv[r];
            }
        }
    };
    auto compute = [&](int buf) {
        const float4* Wb = Wsm + buf * 80 * 16;
        const float*  Xb = Xsm + buf * 16 * 136;
        #pragma unroll
        for (int ci = 0; ci < 16; ci++) {
            const float* row = Xb + ci * 136 + tx * 8;
            float4 q0 = *(const float4*)(row);
            float4 q1 = *(const float4*)(row + 4);
            float4 q2 = *(const float4*)(row + 8);
            float xr[12] = {q0.x,q0.y,q0.z,q0.w, q1.x,q1.y,q1.z,q1.w, q2.x,q2.y,q2.z,q2.w};
            unsigned long long xb[12];
            #pragma unroll
            for (int j = 0; j < 12; j++) xb[j] = bcast2(xr[j]);
            #pragma unroll
            for (int k = 0; k < 5; k++) {
                ulonglong2 wp = *(const ulonglong2*)&Wb[(ci * 5 + k) * 16 + ty];
                #pragma unroll
                for (int jl = 0; jl < 8; jl++) {
                    FMA2(accp[0][jl], wp.x, xb[jl + k]);
                    FMA2(accp[1][jl], wp.y, xb[jl + k]);
                }
            }
        }
    };

    ldW(0); ldX(0); stWX(0);
    __syncthreads();
    #pragma unroll 1
    for (int ch = 0; ch < nCh; ch++) {
        bool more = (ch + 1) < nCh;
        if (more) { ldW(ch + 1); ldX(ch + 1); }
        compute(ch & 1);
        if (more) stWX((ch + 1) & 1);
        __syncthreads();
    }

    #pragma unroll
    for (int p = 0; p < 2; p++) {
        float o[2][8];
        #pragma unroll
        for (int jl = 0; jl < 8; jl++) {
            float2 v = unpack2(accp[p][jl]);
            o[0][jl] = v.x; o[1][jl] = v.y;
        }
        #pragma unroll
        for (int q = 0; q < 2; q++) {
            int co = co0 + ty * 4 + p * 2 + q;
            float bv = bias[co];
            float* op = out + ((size_t)n * CO_ + co) * L_ + l0 + tx * 8;
            *(float4*)(op)     = make_float4(o[q][0]+bv, o[q][1]+bv, o[q][2]+bv, o[q][3]+bv);
            *(float4*)(op + 4) = make_float4(o[q][4]+bv, o[q][5]+bv, o[q][6]+bv, o[q][7]+bv);
        }
    }
}

// ---------------------------------------------------------------------------
// Fused recurrent step. Block tile 16f x 4gates x 64l, 256 thr.
// Double-buffered chunks + epilogue operand prefetch during last chunk.
// dyn smem: Ws4[2][80][16] float4 (40960B) + Xs[2][16][72] float (9216B).
// ---------------------------------------------------------------------------
#define LSTM_SMEM (2*80*16*16 + 2*16*72*4)
__global__ __launch_bounds__(256, 2) void lstm_step_kernel(
    const float* __restrict__ Hprev, // [B, F, L]
    const float* __restrict__ W,     // [CO, CW, 5]
    const float* __restrict__ Ax_t,  // base for this timestep
    size_t axStrideB,                // Ax batch stride (floats)
    const float* __restrict__ Cprev, // [B, F, L]
    float* __restrict__ Cout,        // [B, F, L]
    float* __restrict__ Hout,        // [B, F, L]
    int CW, int choff)
{
    float4* Wsm = (float4*)dynsmem;                              // [2][80][16]
    float*  Xsm = (float*)(dynsmem + 2*80*16*sizeof(float4));    // [2][16][72]

    const int tid = threadIdx.x;
    const int tx = tid & 15, ty = tid >> 4;
    const int l0 = blockIdx.x * 64;
    const int f0 = blockIdx.y * 16;
    const int b  = blockIdx.z;
    const float* Hb = Hprev + (size_t)b * F_ * L_;

    unsigned long long accp[2][4];
    #pragma unroll
    for (int p = 0; p < 2; p++)
        #pragma unroll
        for (int j = 0; j < 4; j++) accp[p][j] = 0ULL;

    const int wRow = tid >> 2, wPart = tid & 3;
    const int gW = wRow >> 4, flW = wRow & 15;
    const int coW = gW * F_ + f0 + flW;

    float4 wv[5];
    float  xv[5];

    auto ldW = [&](int ch) {
        const float4* wp = (const float4*)(W + (size_t)coW * CW * 5
                                             + (size_t)(choff + (ch << 4)) * 5 + wPart * 20);
        #pragma unroll
        for (int e = 0; e < 5; e++) wv[e] = wp[e];
    };
    auto ldX = [&](int ch) {
        const float* Hc = Hb + (size_t)(ch << 4) * L_;
        #pragma unroll
        for (int r = 0; r < 5; r++) {
            int i = tid + (r << 8);
            if (i < 16 * 68) {
                int ci = i / 68, col = i - ci * 68;
                int gl = l0 + col - 2;
                xv[r] = (gl >= 0 && gl < L_) ? Hc[(size_t)ci * L_ + gl] : 0.f;
            }
        }
    };
    auto stWX = [&](int buf) {
        float4* Wb = Wsm + buf * 80 * 16;
        float*  Xb = Xsm + buf * 16 * 72;
        #pragma unroll
        for (int e = 0; e < 5; e++) {
            const float* f = (const float*)&wv[e];
            #pragma unroll
            for (int j = 0; j < 4; j++)
                ((float*)&Wb[(wPart * 20 + e * 4 + j) * 16 + flW])[gW] = f[j];
        }
        #pragma unroll
        for (int r = 0; r < 5; r++) {
            int i = tid + (r << 8);
            if (i < 16 * 68) {
                int ci = i / 68;
                Xb[ci * 72 + (i - ci * 68)] = xv[r];
            }
        }
    };
    auto compute = [&](int buf) {
        const float4* Wb = Wsm + buf * 80 * 16;
        const float*  Xb = Xsm + buf * 16 * 72;
        #pragma unroll
        for (int ci = 0; ci < 16; ci++) {
            const float* row = Xb + ci * 72 + tx * 4;
            float4 q0 = *(const float4*)(row);
            float4 q1 = *(const float4*)(row + 4);
            float xr[8] = {q0.x,q0.y,q0.z,q0.w, q1.x,q1.y,q1.z,q1.w};
            unsigned long long xb[8];
            #pragma unroll
            for (int j = 0; j < 8; j++) xb[j] = bcast2(xr[j]);
            #pragma unroll
            for (int k = 0; k < 5; k++) {
                ulonglong2 wp = *(const ulonglong2*)&Wb[(ci * 5 + k) * 16 + ty];
                #pragma unroll
                for (int jl = 0; jl < 4; jl++) {
                    FMA2(accp[0][jl], wp.x, xb[jl + k]);
                    FMA2(accp[1][jl], wp.y, xb[jl + k]);
                }
            }
        }
    };

    // Epilogue operand prefetch targets
    const int f = f0 + ty;
    const int l = l0 + tx * 4;
    const float* axb = Ax_t + (size_t)b * axStrideB + (size_t)f * L_ + l;
    const size_t idx = ((size_t)b * F_ + f) * L_ + l;
    float4 A0, A1, A2, A3, cp;

    ldW(0); ldX(0); stWX(0);
    __syncthreads();
    #pragma unroll 1
    for (int ch = 0; ch < (F_ >> 4); ch++) {
        bool more = (ch + 1) < (F_ >> 4);
        if (more) {
            ldW(ch + 1); ldX(ch + 1);
        } else {
            A0 = *(const float4*)(axb + (size_t)0 * F_ * L_);
            A1 = *(const float4*)(axb + (size_t)1 * F_ * L_);
            A2 = *(const float4*)(axb + (size_t)2 * F_ * L_);
            A3 = *(const float4*)(axb + (size_t)3 * F_ * L_);
            cp = *(const float4*)&Cprev[idx];
        }
        compute(ch & 1);
        if (more) stWX((ch + 1) & 1);
        __syncthreads();
    }

    // Unpack: accp[0] -> gates 0,1 ; accp[1] -> gates 2,3
    float acc[4][4];
    #pragma unroll
    for (int p = 0; p < 2; p++)
        #pragma unroll
        for (int jl = 0; jl < 4; jl++) {
            float2 v = unpack2(accp[p][jl]);
            acc[2 * p][jl]     = v.x;
            acc[2 * p + 1][jl] = v.y;
        }

    float Ai[4] = {A0.x+acc[0][0], A0.y+acc[0][1], A0.z+acc[0][2], A0.w+acc[0][3]};
    float Af[4] = {A1.x+acc[1][0], A1.y+acc[1][1], A1.z+acc[1][2], A1.w+acc[1][3]};
    float Ao[4] = {A2.x+acc[2][0], A2.y+acc[2][1], A2.z+acc[2][2], A2.w+acc[2][3]};
    float Ag[4] = {A3.x+acc[3][0], A3.y+acc[3][1], A3.z+acc[3][2], A3.w+acc[3][3]};
    float cpv[4] = {cp.x, cp.y, cp.z, cp.w};

    float cn[4], hn[4];
    #pragma unroll
    for (int jl = 0; jl < 4; jl++) {
        float ig = sigm(Ai[jl]);
        float fg = sigm(Af[jl]);
        float og = sigm(Ao[jl]);
        float gg = tanhf(Ag[jl]);
        cn[jl] = fg * cpv[jl] + ig * gg;
        hn[jl] = og * tanhf(cn[jl]);
    }
    *(float4*)&Cout[idx] = make_float4(cn[0], cn[1], cn[2], cn[3]);
    *(float4*)&Hout[idx] = make_float4(hn[0], hn[1], hn[2], hn[3]);
}

// ---------------------------------------------------------------------------
extern "C" void kernel_launch(void* const* d_in, const int* in_sizes, int n_in,
                              void* d_out, int out_size)
{
    const float* x  = (const float*)d_in[0];  // [B, T, Cin, L]
    const float* W0 = (const float*)d_in[1];  // [512, 192, 5]
    const float* b0 = (const float*)d_in[2];  // [512]
    const float* W1 = (const float*)d_in[3];  // [512, 256, 5]
    const float* b1 = (const float*)d_in[4];  // [512]
    const float* h0 = (const float*)d_in[5];  // [B, F, L]
    const float* c0 = (const float*)d_in[6];
    const float* h1 = (const float*)d_in[7];
    const float* c1 = (const float*)d_in[8];
    float* out = (float*)d_out;               // [T, B, F, L]

    static int attr_done = 0;
    if (!attr_done) {
        cudaFuncSetAttribute(conv_gemm_kernel,
                             cudaFuncAttributeMaxDynamicSharedMemorySize, CONV_SMEM);
        cudaFuncSetAttribute(lstm_step_kernel,
                             cudaFuncAttributeMaxDynamicSharedMemorySize, LSTM_SMEM);
        attr_done = 1;
    }

    float *Ax, *hs0, *c0s, *c1s;
    cudaGetSymbolAddress((void**)&Ax,  g_Ax);
    cudaGetSymbolAddress((void**)&hs0, g_hs0);
    cudaGetSymbolAddress((void**)&c0s, g_c0s);
    cudaGetSymbolAddress((void**)&c1s, g_c1s);

    const dim3 blk(256);
    const size_t BFL = (size_t)B_ * F_ * L_;

    // Phase 1: Ax0[n=b*T+t] = bias0 + conv(x_t, W0[:, :Cin])
    conv_gemm_kernel<<<dim3(2, 8, 512), blk, CONV_SMEM>>>(x, W0, b0, Ax, CIN_, CIN_ + F_, 0);

    // Phase 2: layer-0 recurrence. Ax batch index n = b*T + t.
    for (int t = 0; t < T_; t++) {
        const float* Hp = (t == 0) ? h0 : hs0 + (size_t)(t - 1) * BFL;
        const float* Cp = (t == 0) ? c0 : c0s;
        lstm_step_kernel<<<dim3(4, 8, 8), blk, LSTM_SMEM>>>(
            Hp, W0,
            Ax + (size_t)t * CO_ * L_, (size_t)T_ * CO_ * L_,
            Cp, c0s, hs0 + (size_t)t * BFL,
            CIN_ + F_, CIN_);
    }

    // Phase 3: Ax1[n=t*B+b] = bias1 + conv(hs0, W1[:, :F])
    conv_gemm_kernel<<<dim3(2, 8, 512), blk, CONV_SMEM>>>(hs0, W1, b1, Ax, F_, 2 * F_, 0);

    // Phase 4: layer-1 recurrence, writes d_out[t] directly.
    for (int t = 0; t < T_; t++) {
        const float* Hp = (t == 0) ? h1 : out + (size_t)(t - 1) * BFL;
        const float* Cp = (t == 0) ? c1 : c1s;
        lstm_step_kernel<<<dim3(4, 8, 8), blk, LSTM_SMEM>>>(
            Hp, W1,
            Ax + (size_t)t * B_ * CO_ * L_, (size_t)CO_ * L_,
            Cp, c1s, out + (size_t)t * BFL,
            2 * F_, F_);
    }
}